// round 2
// baseline (speedup 1.0000x reference)
#include <cuda_runtime.h>

namespace {
constexpr int BATCH = 8;
constexpr int NA = 1024;     // 32*32 aim positions
constexpr int ND = 4096;     // 64*64 detect positions
constexpr int C  = 512;
constexpr int CI = 256;
constexpr int RA = BATCH * NA;   // 8192  flattened aim rows
constexpr int RD = BATCH * ND;   // 32768 flattened detect rows
constexpr float EPS = 1e-3f;
}

// Scratch (bss, allocation-free)
__device__ float g_dx[(long)RD * CI];      // detect @ Wg
__device__ float g_ax[(long)RA * CI];      // aim @ Wg
__device__ float g_th[(long)RA * CI];      // aim @ Wt
__device__ float g_ph[(long)RD * CI];      // detect @ Wp
__device__ float g_m1[(long)BATCH * CI * CI];  // phi^T @ dx / ND
__device__ float g_m2[(long)BATCH * CI * CI];  // th^T  @ ax / NA
__device__ float g_nap[(long)RA * CI];     // non_aim pre-conv
__device__ float g_ndp[(long)RD * CI];     // non_det pre-conv

// MODE: 0 = plain, 1 = +bias[col], 2 = *scale, 3 = BN(acc+bias)+resid
// TRANS_A: A stored as (K x M) row-major (i.e. compute A^T @ B)
template<int MODE, bool TRANS_A>
__global__ __launch_bounds__(256)
void gemm64(const float* __restrict__ A, const float* __restrict__ Bm,
            float* __restrict__ Cm,
            int M, int N, int K,
            long sA, long sB, long sC,
            const float* __restrict__ bias, float scale,
            const float* __restrict__ gam, const float* __restrict__ beta,
            const float* __restrict__ mean, const float* __restrict__ var,
            const float* __restrict__ resid)
{
    constexpr int BM = 64, BN = 64, BK = 16;
    __shared__ float As[BK][BM];
    __shared__ float Bs[BK][BN];

    const int tid = threadIdx.x;
    const int bz  = blockIdx.z;
    A  += (long)bz * sA;
    Bm += (long)bz * sB;
    Cm += (long)bz * sC;

    const int m0 = blockIdx.y * BM;
    const int n0 = blockIdx.x * BN;

    const int ty = tid >> 4;   // 0..15
    const int tx = tid & 15;   // 0..15

    float acc[4][4] = {};

    for (int k0 = 0; k0 < K; k0 += BK) {
        if (!TRANS_A) {
            // A is (M x K) row-major: load 4 consecutive K per thread, transpose into smem
            const int m  = tid >> 2;          // 0..63
            const int kq = (tid & 3) * 4;     // 0,4,8,12
            float4 v = *reinterpret_cast<const float4*>(&A[(long)(m0 + m) * K + k0 + kq]);
            As[kq + 0][m] = v.x; As[kq + 1][m] = v.y;
            As[kq + 2][m] = v.z; As[kq + 3][m] = v.w;
        } else {
            // A is (K x M) row-major: direct coalesced copy
            const int k  = tid >> 4;          // 0..15
            const int mq = (tid & 15) * 4;
            float4 v = *reinterpret_cast<const float4*>(&A[(long)(k0 + k) * M + m0 + mq]);
            As[k][mq + 0] = v.x; As[k][mq + 1] = v.y;
            As[k][mq + 2] = v.z; As[k][mq + 3] = v.w;
        }
        {
            const int k  = tid >> 4;
            const int nq = (tid & 15) * 4;
            float4 v = *reinterpret_cast<const float4*>(&Bm[(long)(k0 + k) * N + n0 + nq]);
            Bs[k][nq + 0] = v.x; Bs[k][nq + 1] = v.y;
            Bs[k][nq + 2] = v.z; Bs[k][nq + 3] = v.w;
        }
        __syncthreads();

        #pragma unroll
        for (int k = 0; k < BK; ++k) {
            float4 av = *reinterpret_cast<const float4*>(&As[k][ty * 4]);
            float4 bv = *reinterpret_cast<const float4*>(&Bs[k][tx * 4]);
            float a_[4] = {av.x, av.y, av.z, av.w};
            float b_[4] = {bv.x, bv.y, bv.z, bv.w};
            #pragma unroll
            for (int i = 0; i < 4; ++i)
                #pragma unroll
                for (int j = 0; j < 4; ++j)
                    acc[i][j] = fmaf(a_[i], b_[j], acc[i][j]);
        }
        __syncthreads();
    }

    // Epilogue
    #pragma unroll
    for (int i = 0; i < 4; ++i) {
        const int m = m0 + ty * 4 + i;
        const int n = n0 + tx * 4;
        float4 o;
        float* po = &o.x;
        #pragma unroll
        for (int j = 0; j < 4; ++j) {
            float v = acc[i][j];
            const int c = n + j;
            if (MODE == 1) v += bias[c];
            if (MODE == 2) v *= scale;
            if (MODE == 3) {
                const float sc = gam[c] * rsqrtf(var[c] + EPS);
                v = (v + bias[c] - mean[c]) * sc + beta[c] + resid[(long)m * N + c];
            }
            po[j] = v;
        }
        *reinterpret_cast<float4*>(&Cm[(long)m * N + n]) = o;
    }
}

extern "C" void kernel_launch(void* const* d_in, const int* in_sizes, int n_in,
                              void* d_out, int out_size) {
    (void)in_sizes; (void)n_in; (void)out_size;
    const float* detect = (const float*)d_in[0];
    const float* aim    = (const float*)d_in[1];
    const float* Wg  = (const float*)d_in[2];
    const float* bg  = (const float*)d_in[3];
    const float* Wt  = (const float*)d_in[4];
    const float* bt  = (const float*)d_in[5];
    const float* Wp  = (const float*)d_in[6];
    const float* bp  = (const float*)d_in[7];
    const float* Ww  = (const float*)d_in[8];
    const float* bw  = (const float*)d_in[9];
    const float* gw  = (const float*)d_in[10];
    const float* betw= (const float*)d_in[11];
    const float* mw  = (const float*)d_in[12];
    const float* vw  = (const float*)d_in[13];
    const float* Wq  = (const float*)d_in[14];
    const float* bq  = (const float*)d_in[15];
    const float* gq  = (const float*)d_in[16];
    const float* betq= (const float*)d_in[17];
    const float* mq  = (const float*)d_in[18];
    const float* vq  = (const float*)d_in[19];

    float* out    = (float*)d_out;
    float* out_na = out;                      // (RA, C) = non_aim
    float* out_nd = out + (long)RA * C;       // (RD, C) = non_det

    float *dx, *ax, *th, *ph, *m1, *m2, *nap, *ndp;
    cudaGetSymbolAddress((void**)&dx,  g_dx);
    cudaGetSymbolAddress((void**)&ax,  g_ax);
    cudaGetSymbolAddress((void**)&th,  g_th);
    cudaGetSymbolAddress((void**)&ph,  g_ph);
    cudaGetSymbolAddress((void**)&m1,  g_m1);
    cudaGetSymbolAddress((void**)&m2,  g_m2);
    cudaGetSymbolAddress((void**)&nap, g_nap);
    cudaGetSymbolAddress((void**)&ndp, g_ndp);

    const dim3 blk(256);
    const long sPH = (long)ND * CI, sAX = (long)NA * CI, sM = (long)CI * CI;

    // Projections (batch flattened; weights shared)
    gemm64<1,false><<<dim3(CI/64, RD/64, 1), blk>>>(detect, Wg, dx, RD, CI, C,
        0,0,0, bg, 0.f, nullptr,nullptr,nullptr,nullptr,nullptr);
    gemm64<1,false><<<dim3(CI/64, RA/64, 1), blk>>>(aim, Wg, ax, RA, CI, C,
        0,0,0, bg, 0.f, nullptr,nullptr,nullptr,nullptr,nullptr);
    gemm64<1,false><<<dim3(CI/64, RA/64, 1), blk>>>(aim, Wt, th, RA, CI, C,
        0,0,0, bt, 0.f, nullptr,nullptr,nullptr,nullptr,nullptr);
    gemm64<1,false><<<dim3(CI/64, RD/64, 1), blk>>>(detect, Wp, ph, RD, CI, C,
        0,0,0, bp, 0.f, nullptr,nullptr,nullptr,nullptr,nullptr);

    // Inner 256x256 products (associativity: avoids materializing f)
    // m1[b] = phi[b]^T @ dx[b] / ND
    gemm64<2,true><<<dim3(CI/64, CI/64, BATCH), blk>>>(ph, dx, m1, CI, CI, ND,
        sPH, sPH, sM, nullptr, 1.f/(float)ND, nullptr,nullptr,nullptr,nullptr,nullptr);
    // m2[b] = th[b]^T @ ax[b] / NA
    gemm64<2,true><<<dim3(CI/64, CI/64, BATCH), blk>>>(th, ax, m2, CI, CI, NA,
        sAX, sAX, sM, nullptr, 1.f/(float)NA, nullptr,nullptr,nullptr,nullptr,nullptr);

    // Apply: nap[b] = th[b] @ m1[b] ; ndp[b] = ph[b] @ m2[b]
    gemm64<0,false><<<dim3(CI/64, NA/64, BATCH), blk>>>(th, m1, nap, NA, CI, CI,
        sAX, sM, sAX, nullptr, 0.f, nullptr,nullptr,nullptr,nullptr,nullptr);
    gemm64<0,false><<<dim3(CI/64, ND/64, BATCH), blk>>>(ph, m2, ndp, ND, CI, CI,
        sPH, sM, sPH, nullptr, 0.f, nullptr,nullptr,nullptr,nullptr,nullptr);

    // Output convs with fused BN + residual
    gemm64<3,false><<<dim3(C/64, RA/64, 1), blk>>>(nap, Ww, out_na, RA, C, CI,
        0,0,0, bw, 0.f, gw, betw, mw, vw, aim);
    gemm64<3,false><<<dim3(C/64, RD/64, 1), blk>>>(ndp, Wq, out_nd, RD, C, CI,
        0,0,0, bq, 0.f, gq, betq, mq, vq, detect);
}

// round 3
// speedup vs baseline: 2.1134x; 2.1134x over previous
#include <cuda_runtime.h>
#include <cuda_bf16.h>
#include <cstdint>

namespace {
constexpr int BATCH = 8;
constexpr int NA = 1024;
constexpr int ND = 4096;
constexpr int C  = 512;
constexpr int CI = 256;
constexpr int RA = BATCH * NA;   // 8192
constexpr int RD = BATCH * ND;   // 32768
constexpr float EPS = 1e-3f;
constexpr int SPLITK = 8;
}

// Scratch (bss, allocation-free), 16B-aligned for float4 access
__device__ __align__(16) float g_dx[(long)RD * CI];
__device__ __align__(16) float g_ax[(long)RA * CI];
__device__ __align__(16) float g_th[(long)RA * CI];
__device__ __align__(16) float g_ph[(long)RD * CI];
__device__ __align__(16) float g_m1[(long)BATCH * CI * CI];
__device__ __align__(16) float g_m2[(long)BATCH * CI * CI];
__device__ __align__(16) float g_p1[(long)BATCH * SPLITK * CI * CI];
__device__ __align__(16) float g_p2[(long)BATCH * SPLITK * CI * CI];
__device__ __align__(16) float g_nap[(long)RA * CI];
__device__ __align__(16) float g_ndp[(long)RD * CI];

__device__ __forceinline__ void mma_bf16(float* c, const uint32_t* a, uint32_t b0, uint32_t b1) {
    asm volatile(
        "mma.sync.aligned.m16n8k16.row.col.f32.bf16.bf16.f32 "
        "{%0,%1,%2,%3},{%4,%5,%6,%7},{%8,%9},{%0,%1,%2,%3};\n"
        : "+f"(c[0]), "+f"(c[1]), "+f"(c[2]), "+f"(c[3])
        : "r"(a[0]), "r"(a[1]), "r"(a[2]), "r"(a[3]), "r"(b0), "r"(b1));
}
__device__ __forceinline__ void ldsm4(uint32_t* r, uint32_t addr) {
    asm volatile("ldmatrix.sync.aligned.m8n8.x4.shared.b16 {%0,%1,%2,%3},[%4];"
                 : "=r"(r[0]), "=r"(r[1]), "=r"(r[2]), "=r"(r[3]) : "r"(addr));
}
__device__ __forceinline__ void ldsm4t(uint32_t* r, uint32_t addr) {
    asm volatile("ldmatrix.sync.aligned.m8n8.x4.trans.shared.b16 {%0,%1,%2,%3},[%4];"
                 : "=r"(r[0]), "=r"(r[1]), "=r"(r[2]), "=r"(r[3]) : "r"(addr));
}
__device__ __forceinline__ uint32_t pkbf(float a, float b) {
    __nv_bfloat162 v = __floats2bfloat162_rn(a, b);
    return *reinterpret_cast<uint32_t*>(&v);
}
// 8 fp32 -> 8 hi bf16 + 8 lo bf16 (hi = rn(x), lo = rn(x - hi))
__device__ __forceinline__ void split8(float4 u, float4 v, uint4& H, uint4& L) {
    float f[8] = {u.x, u.y, u.z, u.w, v.x, v.y, v.z, v.w};
    float h[8], l[8];
#pragma unroll
    for (int i = 0; i < 8; i++) {
        float hf = __bfloat162float(__float2bfloat16_rn(f[i]));
        h[i] = hf; l[i] = f[i] - hf;
    }
    H = make_uint4(pkbf(h[0], h[1]), pkbf(h[2], h[3]), pkbf(h[4], h[5]), pkbf(h[6], h[7]));
    L = make_uint4(pkbf(l[0], l[1]), pkbf(l[2], l[3]), pkbf(l[4], l[5]), pkbf(l[6], l[7]));
}

// MODE: 0 plain, 1 +bias[col], 2 *scale, 3 BN(acc+bias)+resid
// TRANS_A: A stored (K x M) row-major -> compute A^T @ B
// Block tile 128x128, BK=16, 256 threads (8 warps, warp tile 32x64)
template<int MODE, bool TRANS_A>
__global__ __launch_bounds__(256, 1)
void gemm_mma(const float* __restrict__ A, const float* __restrict__ Bm,
              float* __restrict__ Cm, int M, int N, int K,
              long sA, long sB, long sC,
              const float* __restrict__ bias, float scale,
              const float* __restrict__ gam, const float* __restrict__ beta,
              const float* __restrict__ mean, const float* __restrict__ var,
              const float* __restrict__ resid)
{
    // 2048 uint4 = 32KB: [Ah 2x256][Al 2x256][Bh 2x256][Bl 2x256] chunks of 16B
    __shared__ uint4 smem[2048];
    const int tid = threadIdx.x, lane = tid & 31, warp = tid >> 5;
    const int bz = blockIdx.z;
    A  += (long)bz * sA;
    Bm += (long)bz * sB;
    Cm += (long)bz * sC;
    const int m0 = blockIdx.y * 128, n0 = blockIdx.x * 128;

    // global prefetch pointers (each thread: 8 floats of A, 8 of B per k-tile)
    const float* pA;
    if (!TRANS_A) pA = A + (long)(m0 + (tid >> 1)) * K + (tid & 1) * 8;
    else          pA = A + (long)(tid >> 4) * M + m0 + (tid & 15) * 8;
    const float* pB = Bm + (long)(tid >> 4) * N + n0 + (tid & 15) * 8;
    const long stepA = TRANS_A ? (long)16 * M : 16;
    const long stepB = (long)16 * N;

    // swizzled SMEM store chunk indices
    const int cA = TRANS_A ? ((tid >> 4) * 16 + ((tid & 15) ^ ((tid >> 4) & 7)))
                           : ((tid >> 1) * 2 + ((tid & 1) ^ ((tid >> 3) & 1)));
    const int cB = (tid >> 4) * 16 + ((tid & 15) ^ ((tid >> 4) & 7));

    const int wm0 = (warp >> 1) * 32, wn0 = (warp & 1) * 64;
    const int g = lane >> 3;

    // ldmatrix chunk indices (per thread)
    int aChunk[2];
#pragma unroll
    for (int mt = 0; mt < 2; mt++) {
        if (!TRANS_A) {
            int row = wm0 + mt * 16 + (lane & 7) + (g & 1) * 8;
            int c = g >> 1;
            aChunk[mt] = row * 2 + (c ^ ((row >> 2) & 1));
        } else {
            int row = (lane & 7) + (g >> 1) * 8;
            int c = ((wm0 + mt * 16) >> 3) + (g & 1);
            aChunk[mt] = row * 16 + (c ^ (row & 7));
        }
    }
    int bChunk[4];
#pragma unroll
    for (int np = 0; np < 4; np++) {
        int row = (lane & 7) + (g & 1) * 8;
        int c = ((wn0 + np * 16) >> 3) + (g >> 1);
        bChunk[np] = row * 16 + (c ^ (row & 7));
    }

    const uint32_t sbase = (uint32_t)__cvta_generic_to_shared(smem);
    float acc[2][8][4];
#pragma unroll
    for (int mt = 0; mt < 2; mt++)
#pragma unroll
        for (int nt = 0; nt < 8; nt++)
#pragma unroll
            for (int i = 0; i < 4; i++) acc[mt][nt][i] = 0.f;

    // prologue: tile 0 -> buf 0
    {
        float4 a0 = *(const float4*)(pA);
        float4 a1 = *(const float4*)(pA + 4);
        float4 b0 = *(const float4*)(pB);
        float4 b1 = *(const float4*)(pB + 4);
        uint4 H, L;
        split8(a0, a1, H, L); smem[cA] = H; smem[512 + cA] = L;
        split8(b0, b1, H, L); smem[1024 + cB] = H; smem[1536 + cB] = L;
    }
    __syncthreads();

    const int KT = K >> 4;
    int p = 0;
    float4 fa0, fa1, fb0, fb1;
#pragma unroll 1
    for (int kt = 0; kt < KT; kt++) {
        if (kt + 1 < KT) {
            const float* qA = pA + (long)(kt + 1) * stepA;
            const float* qB = pB + (long)(kt + 1) * stepB;
            fa0 = *(const float4*)(qA); fa1 = *(const float4*)(qA + 4);
            fb0 = *(const float4*)(qB); fb1 = *(const float4*)(qB + 4);
        }
        const uint32_t bo = sbase + p * 4096;
        uint32_t Ah[2][4], Al[2][4], Bh[4][4], Bl[4][4];
#pragma unroll
        for (int mt = 0; mt < 2; mt++) {
            if (!TRANS_A) {
                ldsm4 (Ah[mt], bo + aChunk[mt] * 16);
                ldsm4 (Al[mt], bo + 8192 + aChunk[mt] * 16);
            } else {
                ldsm4t(Ah[mt], bo + aChunk[mt] * 16);
                ldsm4t(Al[mt], bo + 8192 + aChunk[mt] * 16);
            }
        }
#pragma unroll
        for (int np = 0; np < 4; np++) {
            ldsm4t(Bh[np], bo + 16384 + bChunk[np] * 16);
            ldsm4t(Bl[np], bo + 24576 + bChunk[np] * 16);
        }
#pragma unroll
        for (int mt = 0; mt < 2; mt++) {
#pragma unroll
            for (int np = 0; np < 4; np++) {
                const int n2 = np * 2;
                mma_bf16(acc[mt][n2],     Ah[mt], Bh[np][0], Bh[np][1]);
                mma_bf16(acc[mt][n2 + 1], Ah[mt], Bh[np][2], Bh[np][3]);
                mma_bf16(acc[mt][n2],     Ah[mt], Bl[np][0], Bl[np][1]);
                mma_bf16(acc[mt][n2 + 1], Ah[mt], Bl[np][2], Bl[np][3]);
                mma_bf16(acc[mt][n2],     Al[mt], Bh[np][0], Bh[np][1]);
                mma_bf16(acc[mt][n2 + 1], Al[mt], Bh[np][2], Bh[np][3]);
            }
        }
        if (kt + 1 < KT) {
            const int q = p ^ 1;
            uint4 H, L;
            split8(fa0, fa1, H, L); smem[q * 256 + cA] = H; smem[512 + q * 256 + cA] = L;
            split8(fb0, fb1, H, L); smem[1024 + q * 256 + cB] = H; smem[1536 + q * 256 + cB] = L;
            __syncthreads();
            p = q;
        }
    }

    // epilogue
    const int rbase = m0 + wm0 + (lane >> 2);
    const int cbase = n0 + wn0 + (lane & 3) * 2;
#pragma unroll
    for (int mt = 0; mt < 2; mt++) {
#pragma unroll
        for (int nt = 0; nt < 8; nt++) {
            const int col = cbase + nt * 8;
#pragma unroll
            for (int half = 0; half < 2; half++) {
                const int row = rbase + mt * 16 + half * 8;
                float v0 = acc[mt][nt][half * 2];
                float v1 = acc[mt][nt][half * 2 + 1];
                if (MODE == 1) { v0 += bias[col]; v1 += bias[col + 1]; }
                if (MODE == 2) { v0 *= scale;     v1 *= scale; }
                if (MODE == 3) {
                    const float s0 = gam[col] * rsqrtf(var[col] + EPS);
                    const float s1 = gam[col + 1] * rsqrtf(var[col + 1] + EPS);
                    const float2 rr = *(const float2*)&resid[(long)row * N + col];
                    v0 = (v0 + bias[col]     - mean[col])     * s0 + beta[col]     + rr.x;
                    v1 = (v1 + bias[col + 1] - mean[col + 1]) * s1 + beta[col + 1] + rr.y;
                }
                *(float2*)&Cm[(long)row * N + col] = make_float2(v0, v1);
            }
        }
    }
}

// out[b][r] = sum_{s<8} part[(b*8+s)][r], r over CI*CI
__global__ void reduce8(const float* __restrict__ part, float* __restrict__ out) {
    const int nper = CI * CI;
    int i = blockIdx.x * blockDim.x + threadIdx.x;
    if (i >= BATCH * nper) return;
    int b = i / nper, r = i - b * nper;
    const float* p = part + (long)b * SPLITK * nper + r;
    float s = 0.f;
#pragma unroll
    for (int k = 0; k < SPLITK; k++) s += p[(long)k * nper];
    out[i] = s;
}

extern "C" void kernel_launch(void* const* d_in, const int* in_sizes, int n_in,
                              void* d_out, int out_size) {
    (void)in_sizes; (void)n_in; (void)out_size;
    const float* detect = (const float*)d_in[0];
    const float* aim    = (const float*)d_in[1];
    const float* Wg  = (const float*)d_in[2];
    const float* bg  = (const float*)d_in[3];
    const float* Wt  = (const float*)d_in[4];
    const float* bt  = (const float*)d_in[5];
    const float* Wp  = (const float*)d_in[6];
    const float* bp  = (const float*)d_in[7];
    const float* Ww  = (const float*)d_in[8];
    const float* bw  = (const float*)d_in[9];
    const float* gw  = (const float*)d_in[10];
    const float* betw= (const float*)d_in[11];
    const float* mw  = (const float*)d_in[12];
    const float* vw  = (const float*)d_in[13];
    const float* Wq  = (const float*)d_in[14];
    const float* bq  = (const float*)d_in[15];
    const float* gq  = (const float*)d_in[16];
    const float* betq= (const float*)d_in[17];
    const float* mq  = (const float*)d_in[18];
    const float* vq  = (const float*)d_in[19];

    float* out    = (float*)d_out;
    float* out_na = out;
    float* out_nd = out + (long)RA * C;

    float *dx, *ax, *th, *ph, *m1, *m2, *p1, *p2, *nap, *ndp;
    cudaGetSymbolAddress((void**)&dx,  g_dx);
    cudaGetSymbolAddress((void**)&ax,  g_ax);
    cudaGetSymbolAddress((void**)&th,  g_th);
    cudaGetSymbolAddress((void**)&ph,  g_ph);
    cudaGetSymbolAddress((void**)&m1,  g_m1);
    cudaGetSymbolAddress((void**)&m2,  g_m2);
    cudaGetSymbolAddress((void**)&p1,  g_p1);
    cudaGetSymbolAddress((void**)&p2,  g_p2);
    cudaGetSymbolAddress((void**)&nap, g_nap);
    cudaGetSymbolAddress((void**)&ndp, g_ndp);

    const dim3 blk(256);

    // Projections (batch flattened; shared weights)
    gemm_mma<1,false><<<dim3(CI/128, RD/128, 1), blk>>>(detect, Wg, dx, RD, CI, C,
        0,0,0, bg, 0.f, nullptr,nullptr,nullptr,nullptr,nullptr);
    gemm_mma<1,false><<<dim3(CI/128, RA/128, 1), blk>>>(aim, Wg, ax, RA, CI, C,
        0,0,0, bg, 0.f, nullptr,nullptr,nullptr,nullptr,nullptr);
    gemm_mma<1,false><<<dim3(CI/128, RA/128, 1), blk>>>(aim, Wt, th, RA, CI, C,
        0,0,0, bt, 0.f, nullptr,nullptr,nullptr,nullptr,nullptr);
    gemm_mma<1,false><<<dim3(CI/128, RD/128, 1), blk>>>(detect, Wp, ph, RD, CI, C,
        0,0,0, bp, 0.f, nullptr,nullptr,nullptr,nullptr,nullptr);

    // Gram matrices (associativity; split-K x8: bz enumerates (batch, slice),
    // per-bz offset is linear: slice_len*CI floats)
    const long sl1 = (long)(ND / SPLITK) * CI;   // 512*CI
    const long sl2 = (long)(NA / SPLITK) * CI;   // 128*CI
    gemm_mma<2,true><<<dim3(CI/128, CI/128, BATCH*SPLITK), blk>>>(ph, dx, p1,
        CI, CI, ND / SPLITK, sl1, sl1, (long)CI*CI,
        nullptr, 1.f/(float)ND, nullptr,nullptr,nullptr,nullptr,nullptr);
    gemm_mma<2,true><<<dim3(CI/128, CI/128, BATCH*SPLITK), blk>>>(th, ax, p2,
        CI, CI, NA / SPLITK, sl2, sl2, (long)CI*CI,
        nullptr, 1.f/(float)NA, nullptr,nullptr,nullptr,nullptr,nullptr);
    {
        const int n = BATCH * CI * CI;
        reduce8<<<(n + 255) / 256, 256>>>(p1, m1);
        reduce8<<<(n + 255) / 256, 256>>>(p2, m2);
    }

    // Apply: nap[b] = th[b] @ m1[b] ; ndp[b] = ph[b] @ m2[b]
    gemm_mma<0,false><<<dim3(CI/128, NA/128, BATCH), blk>>>(th, m1, nap, NA, CI, CI,
        (long)NA*CI, (long)CI*CI, (long)NA*CI,
        nullptr, 0.f, nullptr,nullptr,nullptr,nullptr,nullptr);
    gemm_mma<0,false><<<dim3(CI/128, ND/128, BATCH), blk>>>(ph, m2, ndp, ND, CI, CI,
        (long)ND*CI, (long)CI*CI, (long)ND*CI,
        nullptr, 0.f, nullptr,nullptr,nullptr,nullptr,nullptr);

    // Output convs with fused BN + residual
    gemm_mma<3,false><<<dim3(C/128, RA/128, 1), blk>>>(nap, Ww, out_na, RA, C, CI,
        0,0,0, bw, 0.f, gw, betw, mw, vw, aim);
    gemm_mma<3,false><<<dim3(C/128, RD/128, 1), blk>>>(ndp, Wq, out_nd, RD, C, CI,
        0,0,0, bq, 0.f, gq, betq, mq, vq, detect);
}

// round 4
// speedup vs baseline: 2.1172x; 1.0018x over previous
#include <cuda_runtime.h>
#include <cuda_bf16.h>
#include <cstdint>

namespace {
constexpr int BATCH = 8;
constexpr int NA = 1024;
constexpr int ND = 4096;
constexpr int C  = 512;
constexpr int CI = 256;
constexpr int RA = BATCH * NA;   // 8192
constexpr int RD = BATCH * ND;   // 32768
constexpr float EPS = 1e-3f;
constexpr int SPLITK = 8;
}

// Scratch (bss, allocation-free), 16B-aligned for float4 access
__device__ __align__(16) float g_dx[(long)RD * CI];
__device__ __align__(16) float g_ax[(long)RA * CI];
__device__ __align__(16) float g_th[(long)RA * CI];
__device__ __align__(16) float g_ph[(long)RD * CI];
__device__ __align__(16) float g_m1[(long)BATCH * CI * CI];
__device__ __align__(16) float g_m2[(long)BATCH * CI * CI];
__device__ __align__(16) float g_p1[(long)BATCH * SPLITK * CI * CI];
__device__ __align__(16) float g_p2[(long)BATCH * SPLITK * CI * CI];
__device__ __align__(16) float g_nap[(long)RA * CI];
__device__ __align__(16) float g_ndp[(long)RD * CI];

__device__ __forceinline__ void mma_bf16(float* c, const uint32_t* a, uint32_t b0, uint32_t b1) {
    asm volatile(
        "mma.sync.aligned.m16n8k16.row.col.f32.bf16.bf16.f32 "
        "{%0,%1,%2,%3},{%4,%5,%6,%7},{%8,%9},{%0,%1,%2,%3};\n"
        : "+f"(c[0]), "+f"(c[1]), "+f"(c[2]), "+f"(c[3])
        : "r"(a[0]), "r"(a[1]), "r"(a[2]), "r"(a[3]), "r"(b0), "r"(b1));
}
__device__ __forceinline__ void ldsm4(uint32_t* r, uint32_t addr) {
    asm volatile("ldmatrix.sync.aligned.m8n8.x4.shared.b16 {%0,%1,%2,%3},[%4];"
                 : "=r"(r[0]), "=r"(r[1]), "=r"(r[2]), "=r"(r[3]) : "r"(addr));
}
__device__ __forceinline__ void ldsm4t(uint32_t* r, uint32_t addr) {
    asm volatile("ldmatrix.sync.aligned.m8n8.x4.trans.shared.b16 {%0,%1,%2,%3},[%4];"
                 : "=r"(r[0]), "=r"(r[1]), "=r"(r[2]), "=r"(r[3]) : "r"(addr));
}
__device__ __forceinline__ uint32_t pkbf(float a, float b) {
    __nv_bfloat162 v = __floats2bfloat162_rn(a, b);
    return *reinterpret_cast<uint32_t*>(&v);
}
// 8 fp32 -> 8 hi bf16 + 8 lo bf16 (hi = rn(x), lo = rn(x - hi))
__device__ __forceinline__ void split8(float4 u, float4 v, uint4& H, uint4& L) {
    float f[8] = {u.x, u.y, u.z, u.w, v.x, v.y, v.z, v.w};
    float h[8], l[8];
#pragma unroll
    for (int i = 0; i < 8; i++) {
        float hf = __bfloat162float(__float2bfloat16_rn(f[i]));
        h[i] = hf; l[i] = f[i] - hf;
    }
    H = make_uint4(pkbf(h[0], h[1]), pkbf(h[2], h[3]), pkbf(h[4], h[5]), pkbf(h[6], h[7]));
    L = make_uint4(pkbf(l[0], l[1]), pkbf(l[2], l[3]), pkbf(l[4], l[5]), pkbf(l[6], l[7]));
}

// MODE: 0 plain, 1 +bias[col], 2 *scale, 3 BN(acc+bias)+resid
// TRANS_A: A stored (K x M) row-major -> compute A^T @ B
// Block tile 128x128, BK=16, 256 threads (8 warps, warp tile 32x64)
template<int MODE, bool TRANS_A>
__global__ __launch_bounds__(256, 1)
void gemm_mma(const float* __restrict__ A, const float* __restrict__ Bm,
              float* __restrict__ Cm, int M, int N, int K,
              long sA, long sB, long sC,
              const float* __restrict__ bias, float scale,
              const float* __restrict__ gam, const float* __restrict__ beta,
              const float* __restrict__ mean, const float* __restrict__ var,
              const float* __restrict__ resid)
{
    // 2048 uint4 = 32KB: [Ah 2x256][Al 2x256][Bh 2x256][Bl 2x256] chunks of 16B
    __shared__ uint4 smem[2048];
    const int tid = threadIdx.x, lane = tid & 31, warp = tid >> 5;
    const int bz = blockIdx.z;
    A  += (long)bz * sA;
    Bm += (long)bz * sB;
    Cm += (long)bz * sC;
    const int m0 = blockIdx.y * 128, n0 = blockIdx.x * 128;

    // global prefetch pointers (each thread: 8 floats of A, 8 of B per k-tile)
    const float* pA;
    if (!TRANS_A) pA = A + (long)(m0 + (tid >> 1)) * K + (tid & 1) * 8;
    else          pA = A + (long)(tid >> 4) * M + m0 + (tid & 15) * 8;
    const float* pB = Bm + (long)(tid >> 4) * N + n0 + (tid & 15) * 8;
    const long stepA = TRANS_A ? (long)16 * M : 16;
    const long stepB = (long)16 * N;

    // swizzled SMEM store chunk indices
    const int cA = TRANS_A ? ((tid >> 4) * 16 + ((tid & 15) ^ ((tid >> 4) & 7)))
                           : ((tid >> 1) * 2 + ((tid & 1) ^ ((tid >> 3) & 1)));
    const int cB = (tid >> 4) * 16 + ((tid & 15) ^ ((tid >> 4) & 7));

    const int wm0 = (warp >> 1) * 32, wn0 = (warp & 1) * 64;
    const int g = lane >> 3;

    // ldmatrix chunk indices (per thread)
    int aChunk[2];
#pragma unroll
    for (int mt = 0; mt < 2; mt++) {
        if (!TRANS_A) {
            int row = wm0 + mt * 16 + (lane & 7) + (g & 1) * 8;
            int c = g >> 1;
            aChunk[mt] = row * 2 + (c ^ ((row >> 2) & 1));
        } else {
            int row = (lane & 7) + (g >> 1) * 8;
            int c = ((wm0 + mt * 16) >> 3) + (g & 1);
            aChunk[mt] = row * 16 + (c ^ (row & 7));
        }
    }
    int bChunk[4];
#pragma unroll
    for (int np = 0; np < 4; np++) {
        int row = (lane & 7) + (g & 1) * 8;
        int c = ((wn0 + np * 16) >> 3) + (g >> 1);
        bChunk[np] = row * 16 + (c ^ (row & 7));
    }

    const uint32_t sbase = (uint32_t)__cvta_generic_to_shared(smem);
    float acc[2][8][4];
#pragma unroll
    for (int mt = 0; mt < 2; mt++)
#pragma unroll
        for (int nt = 0; nt < 8; nt++)
#pragma unroll
            for (int i = 0; i < 4; i++) acc[mt][nt][i] = 0.f;

    // prologue: tile 0 -> buf 0
    {
        float4 a0 = *(const float4*)(pA);
        float4 a1 = *(const float4*)(pA + 4);
        float4 b0 = *(const float4*)(pB);
        float4 b1 = *(const float4*)(pB + 4);
        uint4 H, L;
        split8(a0, a1, H, L); smem[cA] = H; smem[512 + cA] = L;
        split8(b0, b1, H, L); smem[1024 + cB] = H; smem[1536 + cB] = L;
    }
    __syncthreads();

    const int KT = K >> 4;
    int p = 0;
    float4 fa0, fa1, fb0, fb1;
#pragma unroll 1
    for (int kt = 0; kt < KT; kt++) {
        if (kt + 1 < KT) {
            const float* qA = pA + (long)(kt + 1) * stepA;
            const float* qB = pB + (long)(kt + 1) * stepB;
            fa0 = *(const float4*)(qA); fa1 = *(const float4*)(qA + 4);
            fb0 = *(const float4*)(qB); fb1 = *(const float4*)(qB + 4);
        }
        const uint32_t bo = sbase + p * 4096;
        uint32_t Ah[2][4], Al[2][4], Bh[4][4], Bl[4][4];
#pragma unroll
        for (int mt = 0; mt < 2; mt++) {
            if (!TRANS_A) {
                ldsm4 (Ah[mt], bo + aChunk[mt] * 16);
                ldsm4 (Al[mt], bo + 8192 + aChunk[mt] * 16);
            } else {
                ldsm4t(Ah[mt], bo + aChunk[mt] * 16);
                ldsm4t(Al[mt], bo + 8192 + aChunk[mt] * 16);
            }
        }
#pragma unroll
        for (int np = 0; np < 4; np++) {
            ldsm4t(Bh[np], bo + 16384 + bChunk[np] * 16);
            ldsm4t(Bl[np], bo + 24576 + bChunk[np] * 16);
        }
#pragma unroll
        for (int mt = 0; mt < 2; mt++) {
#pragma unroll
            for (int np = 0; np < 4; np++) {
                const int n2 = np * 2;
                mma_bf16(acc[mt][n2],     Ah[mt], Bh[np][0], Bh[np][1]);
                mma_bf16(acc[mt][n2 + 1], Ah[mt], Bh[np][2], Bh[np][3]);
                mma_bf16(acc[mt][n2],     Ah[mt], Bl[np][0], Bl[np][1]);
                mma_bf16(acc[mt][n2 + 1], Ah[mt], Bl[np][2], Bl[np][3]);
                mma_bf16(acc[mt][n2],     Al[mt], Bh[np][0], Bh[np][1]);
                mma_bf16(acc[mt][n2 + 1], Al[mt], Bh[np][2], Bh[np][3]);
            }
        }
        if (kt + 1 < KT) {
            const int q = p ^ 1;
            uint4 H, L;
            split8(fa0, fa1, H, L); smem[q * 256 + cA] = H; smem[512 + q * 256 + cA] = L;
            split8(fb0, fb1, H, L); smem[1024 + q * 256 + cB] = H; smem[1536 + q * 256 + cB] = L;
            __syncthreads();
            p = q;
        }
    }

    // epilogue
    const int rbase = m0 + wm0 + (lane >> 2);
    const int cbase = n0 + wn0 + (lane & 3) * 2;
#pragma unroll
    for (int mt = 0; mt < 2; mt++) {
#pragma unroll
        for (int nt = 0; nt < 8; nt++) {
            const int col = cbase + nt * 8;
#pragma unroll
            for (int half = 0; half < 2; half++) {
                const int row = rbase + mt * 16 + half * 8;
                float v0 = acc[mt][nt][half * 2];
                float v1 = acc[mt][nt][half * 2 + 1];
                if (MODE == 1) { v0 += bias[col]; v1 += bias[col + 1]; }
                if (MODE == 2) { v0 *= scale;     v1 *= scale; }
                if (MODE == 3) {
                    const float s0 = gam[col] * rsqrtf(var[col] + EPS);
                    const float s1 = gam[col + 1] * rsqrtf(var[col + 1] + EPS);
                    const float2 rr = *(const float2*)&resid[(long)row * N + col];
                    v0 = (v0 + bias[col]     - mean[col])     * s0 + beta[col]     + rr.x;
                    v1 = (v1 + bias[col + 1] - mean[col + 1]) * s1 + beta[col + 1] + rr.y;
                }
                *(float2*)&Cm[(long)row * N + col] = make_float2(v0, v1);
            }
        }
    }
}

// out[b][r] = sum_{s<8} part[(b*8+s)][r], r over CI*CI
__global__ void reduce8(const float* __restrict__ part, float* __restrict__ out) {
    const int nper = CI * CI;
    int i = blockIdx.x * blockDim.x + threadIdx.x;
    if (i >= BATCH * nper) return;
    int b = i / nper, r = i - b * nper;
    const float* p = part + (long)b * SPLITK * nper + r;
    float s = 0.f;
#pragma unroll
    for (int k = 0; k < SPLITK; k++) s += p[(long)k * nper];
    out[i] = s;
}

extern "C" void kernel_launch(void* const* d_in, const int* in_sizes, int n_in,
                              void* d_out, int out_size) {
    (void)in_sizes; (void)n_in; (void)out_size;
    const float* detect = (const float*)d_in[0];
    const float* aim    = (const float*)d_in[1];
    const float* Wg  = (const float*)d_in[2];
    const float* bg  = (const float*)d_in[3];
    const float* Wt  = (const float*)d_in[4];
    const float* bt  = (const float*)d_in[5];
    const float* Wp  = (const float*)d_in[6];
    const float* bp  = (const float*)d_in[7];
    const float* Ww  = (const float*)d_in[8];
    const float* bw  = (const float*)d_in[9];
    const float* gw  = (const float*)d_in[10];
    const float* betw= (const float*)d_in[11];
    const float* mw  = (const float*)d_in[12];
    const float* vw  = (const float*)d_in[13];
    const float* Wq  = (const float*)d_in[14];
    const float* bq  = (const float*)d_in[15];
    const float* gq  = (const float*)d_in[16];
    const float* betq= (const float*)d_in[17];
    const float* mq  = (const float*)d_in[18];
    const float* vq  = (const float*)d_in[19];

    float* out    = (float*)d_out;
    float* out_na = out;
    float* out_nd = out + (long)RA * C;

    float *dx, *ax, *th, *ph, *m1, *m2, *p1, *p2, *nap, *ndp;
    cudaGetSymbolAddress((void**)&dx,  g_dx);
    cudaGetSymbolAddress((void**)&ax,  g_ax);
    cudaGetSymbolAddress((void**)&th,  g_th);
    cudaGetSymbolAddress((void**)&ph,  g_ph);
    cudaGetSymbolAddress((void**)&m1,  g_m1);
    cudaGetSymbolAddress((void**)&m2,  g_m2);
    cudaGetSymbolAddress((void**)&p1,  g_p1);
    cudaGetSymbolAddress((void**)&p2,  g_p2);
    cudaGetSymbolAddress((void**)&nap, g_nap);
    cudaGetSymbolAddress((void**)&ndp, g_ndp);

    const dim3 blk(256);

    // Projections (batch flattened; shared weights)
    gemm_mma<1,false><<<dim3(CI/128, RD/128, 1), blk>>>(detect, Wg, dx, RD, CI, C,
        0,0,0, bg, 0.f, nullptr,nullptr,nullptr,nullptr,nullptr);
    gemm_mma<1,false><<<dim3(CI/128, RA/128, 1), blk>>>(aim, Wg, ax, RA, CI, C,
        0,0,0, bg, 0.f, nullptr,nullptr,nullptr,nullptr,nullptr);
    gemm_mma<1,false><<<dim3(CI/128, RA/128, 1), blk>>>(aim, Wt, th, RA, CI, C,
        0,0,0, bt, 0.f, nullptr,nullptr,nullptr,nullptr,nullptr);
    gemm_mma<1,false><<<dim3(CI/128, RD/128, 1), blk>>>(detect, Wp, ph, RD, CI, C,
        0,0,0, bp, 0.f, nullptr,nullptr,nullptr,nullptr,nullptr);

    // Gram matrices (associativity; split-K x8: bz enumerates (batch, slice),
    // per-bz offset is linear: slice_len*CI floats)
    const long sl1 = (long)(ND / SPLITK) * CI;   // 512*CI
    const long sl2 = (long)(NA / SPLITK) * CI;   // 128*CI
    gemm_mma<2,true><<<dim3(CI/128, CI/128, BATCH*SPLITK), blk>>>(ph, dx, p1,
        CI, CI, ND / SPLITK, sl1, sl1, (long)CI*CI,
        nullptr, 1.f/(float)ND, nullptr,nullptr,nullptr,nullptr,nullptr);
    gemm_mma<2,true><<<dim3(CI/128, CI/128, BATCH*SPLITK), blk>>>(th, ax, p2,
        CI, CI, NA / SPLITK, sl2, sl2, (long)CI*CI,
        nullptr, 1.f/(float)NA, nullptr,nullptr,nullptr,nullptr,nullptr);
    {
        const int n = BATCH * CI * CI;
        reduce8<<<(n + 255) / 256, 256>>>(p1, m1);
        reduce8<<<(n + 255) / 256, 256>>>(p2, m2);
    }

    // Apply: nap[b] = th[b] @ m1[b] ; ndp[b] = ph[b] @ m2[b]
    gemm_mma<0,false><<<dim3(CI/128, NA/128, BATCH), blk>>>(th, m1, nap, NA, CI, CI,
        (long)NA*CI, (long)CI*CI, (long)NA*CI,
        nullptr, 0.f, nullptr,nullptr,nullptr,nullptr,nullptr);
    gemm_mma<0,false><<<dim3(CI/128, ND/128, BATCH), blk>>>(ph, m2, ndp, ND, CI, CI,
        (long)ND*CI, (long)CI*CI, (long)ND*CI,
        nullptr, 0.f, nullptr,nullptr,nullptr,nullptr,nullptr);

    // Output convs with fused BN + residual
    gemm_mma<3,false><<<dim3(C/128, RA/128, 1), blk>>>(nap, Ww, out_na, RA, C, CI,
        0,0,0, bw, 0.f, gw, betw, mw, vw, aim);
    gemm_mma<3,false><<<dim3(C/128, RD/128, 1), blk>>>(ndp, Wq, out_nd, RD, C, CI,
        0,0,0, bq, 0.f, gq, betq, mq, vq, detect);
}

// round 6
// speedup vs baseline: 3.0651x; 1.4477x over previous
#include <cuda_runtime.h>
#include <cuda_bf16.h>
#include <cstdint>

using bf16 = __nv_bfloat16;

namespace {
constexpr int BATCH=8, NA=1024, ND=4096, C=512, CI=256;
constexpr int RA=BATCH*NA, RD=BATCH*ND;
constexpr float EPS=1e-3f;
constexpr int SPLITK=8;
constexpr int STAGE_B = 16384;           // Ah4K|Al4K|Bh4K|Bl4K per stage
constexpr int SMEM_BYTES = 4*STAGE_B;    // 64KB, 4 stages
}

// ---- bf16 hi/lo split buffers (bss) ----
__device__ __align__(16) bf16 g_detH[(long)RD*C], g_detL[(long)RD*C];
__device__ __align__(16) bf16 g_aimH[(long)RA*C], g_aimL[(long)RA*C];
__device__ __align__(16) bf16 g_WgH[C*CI], g_WgL[C*CI];
__device__ __align__(16) bf16 g_WtH[C*CI], g_WtL[C*CI];
__device__ __align__(16) bf16 g_WpH[C*CI], g_WpL[C*CI];
__device__ __align__(16) bf16 g_WwH[CI*C], g_WwL[CI*C];
__device__ __align__(16) bf16 g_WqH[CI*C], g_WqL[CI*C];
__device__ __align__(16) bf16 g_dxH[(long)RD*CI], g_dxL[(long)RD*CI];
__device__ __align__(16) bf16 g_phH[(long)RD*CI], g_phL[(long)RD*CI];
__device__ __align__(16) bf16 g_axH[(long)RA*CI], g_axL[(long)RA*CI];
__device__ __align__(16) bf16 g_thH[(long)RA*CI], g_thL[(long)RA*CI];
__device__ __align__(16) float g_p1[(long)BATCH*SPLITK*CI*CI];
__device__ __align__(16) float g_p2[(long)BATCH*SPLITK*CI*CI];
__device__ __align__(16) bf16 g_m1H[(long)BATCH*CI*CI], g_m1L[(long)BATCH*CI*CI];
__device__ __align__(16) bf16 g_m2H[(long)BATCH*CI*CI], g_m2L[(long)BATCH*CI*CI];
__device__ __align__(16) bf16 g_napH[(long)RA*CI], g_napL[(long)RA*CI];
__device__ __align__(16) bf16 g_ndpH[(long)RD*CI], g_ndpL[(long)RD*CI];

__device__ __forceinline__ void mma_bf16(float* c, const uint32_t* a, uint32_t b0, uint32_t b1){
    asm volatile("mma.sync.aligned.m16n8k16.row.col.f32.bf16.bf16.f32 "
        "{%0,%1,%2,%3},{%4,%5,%6,%7},{%8,%9},{%0,%1,%2,%3};\n"
        : "+f"(c[0]),"+f"(c[1]),"+f"(c[2]),"+f"(c[3])
        : "r"(a[0]),"r"(a[1]),"r"(a[2]),"r"(a[3]),"r"(b0),"r"(b1));
}
__device__ __forceinline__ void ldsm4(uint32_t* r, uint32_t a){
    asm volatile("ldmatrix.sync.aligned.m8n8.x4.shared.b16 {%0,%1,%2,%3},[%4];"
        : "=r"(r[0]),"=r"(r[1]),"=r"(r[2]),"=r"(r[3]) : "r"(a));
}
__device__ __forceinline__ void ldsm4t(uint32_t* r, uint32_t a){
    asm volatile("ldmatrix.sync.aligned.m8n8.x4.trans.shared.b16 {%0,%1,%2,%3},[%4];"
        : "=r"(r[0]),"=r"(r[1]),"=r"(r[2]),"=r"(r[3]) : "r"(a));
}
__device__ __forceinline__ void cpa16(uint32_t dst, const void* src){
    asm volatile("cp.async.cg.shared.global [%0], [%1], 16;" :: "r"(dst),"l"(src));
}
#define CP_COMMIT() asm volatile("cp.async.commit_group;")
#define CP_WAIT2()  asm volatile("cp.async.wait_group 2;")

// MODE: 0 plain, 1 +bias, 2 *scale, 3 BN(acc+bias)+resid
// TA: A stored (K x M) -> compute A^T @ B.   B always stored (K x N).
// OUTB: write bf16 hi/lo pair outputs; else fp32.
template<int MODE, bool TA, bool OUTB>
__global__ __launch_bounds__(256, 2)
void gemm_cp(const bf16* __restrict__ AH, const bf16* __restrict__ AL,
             const bf16* __restrict__ BH, const bf16* __restrict__ BL,
             float* __restrict__ Cf, bf16* __restrict__ CH, bf16* __restrict__ CL,
             int K, long lda, long ldb, long ldc,
             long zA, long zB, long zC,
             const float* __restrict__ bias, float scale,
             const float* __restrict__ gam, const float* __restrict__ beta,
             const float* __restrict__ mean, const float* __restrict__ var,
             const float* __restrict__ resid)
{
    extern __shared__ __align__(128) char smem[];
    const int tid=threadIdx.x, lane=tid&31, warp=tid>>5;
    const int z=blockIdx.z;
    AH += (long)z*zA; AL += (long)z*zA;
    BH += (long)z*zB; BL += (long)z*zB;
    const long co = (long)z*zC;
    const int m0 = blockIdx.y*128, n0 = blockIdx.x*128;
    const uint32_t sb = (uint32_t)__cvta_generic_to_shared(smem);

    // per-thread cp.async src/dst
    const bf16 *pAH, *pAL, *pBH, *pBL;
    uint32_t dA, dB;
    long stepA, stepB;
    if (!TA){
        const int row=tid>>1, k8=tid&1;
        const long o = (long)(m0+row)*lda + k8*8;
        pAH = AH+o; pAL = AL+o;
        dA = (uint32_t)(row*2 + (k8 ^ ((row>>2)&1)))*16;
        stepA = 16;
    } else {
        const int k=tid>>4, m8=tid&15;
        const long o = (long)k*lda + m0 + m8*8;
        pAH = AH+o; pAL = AL+o;
        dA = (uint32_t)(k*16 + (m8 ^ (k&7)))*16;
        stepA = 16*lda;
    }
    {
        const int k=tid>>4, n8=tid&15;
        const long o = (long)k*ldb + n0 + n8*8;
        pBH = BH+o; pBL = BL+o;
        dB = (uint32_t)(k*16 + (n8 ^ (k&7)))*16;
        stepB = 16*ldb;
    }

    // ldsm chunk indices
    const int wm0 = (warp>>1)*32, wn0 = (warp&1)*64;
    const int g = lane>>3;
    int aChunk[2];
#pragma unroll
    for (int mt=0; mt<2; mt++){
        if (!TA){
            const int row = wm0 + mt*16 + (lane&7) + (g&1)*8;
            aChunk[mt] = row*2 + ((g>>1) ^ ((row>>2)&1));
        } else {
            const int row = (lane&7) + (g>>1)*8;
            const int c = ((wm0 + mt*16)>>3) + (g&1);
            aChunk[mt] = row*16 + (c ^ (row&7));
        }
    }
    int bChunk[4];
#pragma unroll
    for (int np=0; np<4; np++){
        const int row = (lane&7) + (g&1)*8;
        const int c = ((wn0 + np*16)>>3) + (g>>1);
        bChunk[np] = row*16 + (c ^ (row&7));
    }

    float acc[2][8][4];
#pragma unroll
    for (int mt=0;mt<2;mt++)
#pragma unroll
        for (int nt=0;nt<8;nt++)
#pragma unroll
            for (int i=0;i<4;i++) acc[mt][nt][i]=0.f;

    const int NC = K>>4;
    // prologue: stages 0..2
#pragma unroll
    for (int c=0; c<3; c++){
        const uint32_t ba = sb + (c&3)*STAGE_B;
        cpa16(ba         + dA, pAH + (long)c*stepA);
        cpa16(ba + 4096  + dA, pAL + (long)c*stepA);
        cpa16(ba + 8192  + dB, pBH + (long)c*stepB);
        cpa16(ba + 12288 + dB, pBL + (long)c*stepB);
        CP_COMMIT();
    }

#pragma unroll 1
    for (int c=0; c<NC; c++){
        CP_WAIT2();
        __syncthreads();
        if (c+3 < NC){
            const uint32_t ba = sb + ((c+3)&3)*STAGE_B;
            cpa16(ba         + dA, pAH + (long)(c+3)*stepA);
            cpa16(ba + 4096  + dA, pAL + (long)(c+3)*stepA);
            cpa16(ba + 8192  + dB, pBH + (long)(c+3)*stepB);
            cpa16(ba + 12288 + dB, pBL + (long)(c+3)*stepB);
        }
        CP_COMMIT();

        const uint32_t ba = sb + (c&3)*STAGE_B;
        uint32_t Ah[2][4], Al[2][4];
#pragma unroll
        for (int mt=0; mt<2; mt++){
            if (!TA){
                ldsm4 (Ah[mt], ba + aChunk[mt]*16);
                ldsm4 (Al[mt], ba + 4096 + aChunk[mt]*16);
            } else {
                ldsm4t(Ah[mt], ba + aChunk[mt]*16);
                ldsm4t(Al[mt], ba + 4096 + aChunk[mt]*16);
            }
        }
#pragma unroll
        for (int np=0; np<4; np++){
            uint32_t Bh[4], Bl[4];
            ldsm4t(Bh, ba + 8192  + bChunk[np]*16);
            ldsm4t(Bl, ba + 12288 + bChunk[np]*16);
            const int n2 = np*2;
#pragma unroll
            for (int mt=0; mt<2; mt++){
                mma_bf16(acc[mt][n2],   Ah[mt], Bh[0], Bh[1]);
                mma_bf16(acc[mt][n2+1], Ah[mt], Bh[2], Bh[3]);
                mma_bf16(acc[mt][n2],   Ah[mt], Bl[0], Bl[1]);
                mma_bf16(acc[mt][n2+1], Ah[mt], Bl[2], Bl[3]);
                mma_bf16(acc[mt][n2],   Al[mt], Bh[0], Bh[1]);
                mma_bf16(acc[mt][n2+1], Al[mt], Bh[2], Bh[3]);
            }
        }
    }

    // epilogue
    const int rbase = m0 + wm0 + (lane>>2);
    const int cbase = n0 + wn0 + (lane&3)*2;
#pragma unroll
    for (int mt=0; mt<2; mt++){
#pragma unroll
        for (int nt=0; nt<8; nt++){
            const int col = cbase + nt*8;
#pragma unroll
            for (int half=0; half<2; half++){
                const int row = rbase + mt*16 + half*8;
                float v0 = acc[mt][nt][half*2];
                float v1 = acc[mt][nt][half*2+1];
                if (MODE==1){ v0 += bias[col]; v1 += bias[col+1]; }
                if (MODE==2){ v0 *= scale;     v1 *= scale; }
                if (MODE==3){
                    const float s0 = gam[col]  *rsqrtf(var[col]  +EPS);
                    const float s1 = gam[col+1]*rsqrtf(var[col+1]+EPS);
                    const float2 rr = *(const float2*)&resid[co + (long)row*ldc + col];
                    v0 = (v0 + bias[col]  - mean[col])  *s0 + beta[col]   + rr.x;
                    v1 = (v1 + bias[col+1]- mean[col+1])*s1 + beta[col+1] + rr.y;
                }
                const long gidx = co + (long)row*ldc + col;
                if (OUTB){
                    const bf16 h0 = __float2bfloat16_rn(v0);
                    const bf16 h1 = __float2bfloat16_rn(v1);
                    const bf16 l0 = __float2bfloat16_rn(v0 - __bfloat162float(h0));
                    const bf16 l1 = __float2bfloat16_rn(v1 - __bfloat162float(h1));
                    __nv_bfloat162 hp = {h0,h1}, lp = {l0,l1};
                    *(uint32_t*)&CH[gidx] = *(uint32_t*)&hp;
                    *(uint32_t*)&CL[gidx] = *(uint32_t*)&lp;
                } else {
                    *(float2*)&Cf[gidx] = make_float2(v0, v1);
                }
            }
        }
    }
}

__global__ __launch_bounds__(256) void fsplit(const float* __restrict__ x,
                                              bf16* __restrict__ h, bf16* __restrict__ l, int n4){
    const int i = blockIdx.x*256 + threadIdx.x;
    if (i >= n4) return;
    const float4 v = ((const float4*)x)[i];
    const float f[4] = {v.x,v.y,v.z,v.w};
    bf16 hh[4], ll[4];
#pragma unroll
    for (int j=0;j<4;j++){
        hh[j] = __float2bfloat16_rn(f[j]);
        ll[j] = __float2bfloat16_rn(f[j] - __bfloat162float(hh[j]));
    }
    ((uint2*)h)[i] = *(uint2*)hh;
    ((uint2*)l)[i] = *(uint2*)ll;
}

__global__ void reduce8b(const float* __restrict__ part, bf16* __restrict__ oh, bf16* __restrict__ ol){
    const int nper = CI*CI;
    const int i = blockIdx.x*blockDim.x + threadIdx.x;
    if (i >= BATCH*nper) return;
    const int b = i/nper, r = i - b*nper;
    const float* p = part + (long)b*SPLITK*nper + r;
    float s = 0.f;
#pragma unroll
    for (int k=0;k<SPLITK;k++) s += p[(long)k*nper];
    const bf16 h = __float2bfloat16_rn(s);
    oh[i] = h;
    ol[i] = __float2bfloat16_rn(s - __bfloat162float(h));
}

#define SYM(p, s) cudaGetSymbolAddress((void**)&p, s)

extern "C" void kernel_launch(void* const* d_in, const int* in_sizes, int n_in,
                              void* d_out, int out_size){
    (void)in_sizes; (void)n_in; (void)out_size;
    const float* detect=(const float*)d_in[0];
    const float* aim   =(const float*)d_in[1];
    const float* Wg=(const float*)d_in[2];  const float* bg=(const float*)d_in[3];
    const float* Wt=(const float*)d_in[4];  const float* bt=(const float*)d_in[5];
    const float* Wp=(const float*)d_in[6];  const float* bp=(const float*)d_in[7];
    const float* Ww=(const float*)d_in[8];  const float* bw=(const float*)d_in[9];
    const float* gw=(const float*)d_in[10]; const float* betw=(const float*)d_in[11];
    const float* mw=(const float*)d_in[12]; const float* vw=(const float*)d_in[13];
    const float* Wq=(const float*)d_in[14]; const float* bq=(const float*)d_in[15];
    const float* gq=(const float*)d_in[16]; const float* betq=(const float*)d_in[17];
    const float* mq=(const float*)d_in[18]; const float* vq=(const float*)d_in[19];

    float* out    = (float*)d_out;
    float* out_na = out;
    float* out_nd = out + (long)RA*C;

    bf16 *detH,*detL,*aimH,*aimL,*WgH,*WgL,*WtH,*WtL,*WpH,*WpL,*WwH,*WwL,*WqH,*WqL;
    bf16 *dxH,*dxL,*phH,*phL,*axH,*axL,*thH,*thL,*m1H,*m1L,*m2H,*m2L,*napH,*napL,*ndpH,*ndpL;
    float *p1,*p2;
    SYM(detH,g_detH); SYM(detL,g_detL); SYM(aimH,g_aimH); SYM(aimL,g_aimL);
    SYM(WgH,g_WgH); SYM(WgL,g_WgL); SYM(WtH,g_WtH); SYM(WtL,g_WtL);
    SYM(WpH,g_WpH); SYM(WpL,g_WpL); SYM(WwH,g_WwH); SYM(WwL,g_WwL);
    SYM(WqH,g_WqH); SYM(WqL,g_WqL);
    SYM(dxH,g_dxH); SYM(dxL,g_dxL); SYM(phH,g_phH); SYM(phL,g_phL);
    SYM(axH,g_axH); SYM(axL,g_axL); SYM(thH,g_thH); SYM(thL,g_thL);
    SYM(m1H,g_m1H); SYM(m1L,g_m1L); SYM(m2H,g_m2H); SYM(m2L,g_m2L);
    SYM(napH,g_napH); SYM(napL,g_napL); SYM(ndpH,g_ndpH); SYM(ndpL,g_ndpL);
    SYM(p1,g_p1); SYM(p2,g_p2);

    cudaFuncSetAttribute(gemm_cp<1,false,true >, cudaFuncAttributeMaxDynamicSharedMemorySize, SMEM_BYTES);
    cudaFuncSetAttribute(gemm_cp<2,true ,false>, cudaFuncAttributeMaxDynamicSharedMemorySize, SMEM_BYTES);
    cudaFuncSetAttribute(gemm_cp<0,false,true >, cudaFuncAttributeMaxDynamicSharedMemorySize, SMEM_BYTES);
    cudaFuncSetAttribute(gemm_cp<3,false,false>, cudaFuncAttributeMaxDynamicSharedMemorySize, SMEM_BYTES);

    const dim3 blk(256);

    // prepass splits
    fsplit<<<(RD*C/4+255)/256, 256>>>(detect, detH, detL, RD*C/4);
    fsplit<<<(RA*C/4+255)/256, 256>>>(aim,    aimH, aimL, RA*C/4);
    fsplit<<<(C*CI/4+255)/256, 256>>>(Wg, WgH, WgL, C*CI/4);
    fsplit<<<(C*CI/4+255)/256, 256>>>(Wt, WtH, WtL, C*CI/4);
    fsplit<<<(C*CI/4+255)/256, 256>>>(Wp, WpH, WpL, C*CI/4);
    fsplit<<<(CI*C/4+255)/256, 256>>>(Ww, WwH, WwL, CI*C/4);
    fsplit<<<(CI*C/4+255)/256, 256>>>(Wq, WqH, WqL, CI*C/4);

    const long sM = (long)CI*CI;

    // projections: X @ W + b  -> bf16 pairs
    gemm_cp<1,false,true><<<dim3(2,RD/128,1),blk,SMEM_BYTES>>>(detH,detL,WgH,WgL,
        nullptr,dxH,dxL, C, C,CI,CI, 0,0,0, bg,0.f,nullptr,nullptr,nullptr,nullptr,nullptr);
    gemm_cp<1,false,true><<<dim3(2,RD/128,1),blk,SMEM_BYTES>>>(detH,detL,WpH,WpL,
        nullptr,phH,phL, C, C,CI,CI, 0,0,0, bp,0.f,nullptr,nullptr,nullptr,nullptr,nullptr);
    gemm_cp<1,false,true><<<dim3(2,RA/128,1),blk,SMEM_BYTES>>>(aimH,aimL,WgH,WgL,
        nullptr,axH,axL, C, C,CI,CI, 0,0,0, bg,0.f,nullptr,nullptr,nullptr,nullptr,nullptr);
    gemm_cp<1,false,true><<<dim3(2,RA/128,1),blk,SMEM_BYTES>>>(aimH,aimL,WtH,WtL,
        nullptr,thH,thL, C, C,CI,CI, 0,0,0, bt,0.f,nullptr,nullptr,nullptr,nullptr,nullptr);

    // gram: m1 = ph^T dx / ND ; m2 = th^T ax / NA  (split-K x8, fp32 partials)
    gemm_cp<2,true,false><<<dim3(2,2,BATCH*SPLITK),blk,SMEM_BYTES>>>(phH,phL,dxH,dxL,
        p1,nullptr,nullptr, ND/SPLITK, CI,CI,CI,
        (long)(ND/SPLITK)*CI,(long)(ND/SPLITK)*CI,sM,
        nullptr,1.f/(float)ND,nullptr,nullptr,nullptr,nullptr,nullptr);
    gemm_cp<2,true,false><<<dim3(2,2,BATCH*SPLITK),blk,SMEM_BYTES>>>(thH,thL,axH,axL,
        p2,nullptr,nullptr, NA/SPLITK, CI,CI,CI,
        (long)(NA/SPLITK)*CI,(long)(NA/SPLITK)*CI,sM,
        nullptr,1.f/(float)NA,nullptr,nullptr,nullptr,nullptr,nullptr);
    {
        const int n = BATCH*CI*CI;
        reduce8b<<<(n+255)/256,256>>>(p1, m1H, m1L);
        reduce8b<<<(n+255)/256,256>>>(p2, m2H, m2L);
    }

    // apply: nap = th @ m1 ; ndp = ph @ m2  -> bf16 pairs
    gemm_cp<0,false,true><<<dim3(2,NA/128,BATCH),blk,SMEM_BYTES>>>(thH,thL,m1H,m1L,
        nullptr,napH,napL, CI, CI,CI,CI, (long)NA*CI,sM,(long)NA*CI,
        nullptr,0.f,nullptr,nullptr,nullptr,nullptr,nullptr);
    gemm_cp<0,false,true><<<dim3(2,ND/128,BATCH),blk,SMEM_BYTES>>>(phH,phL,m2H,m2L,
        nullptr,ndpH,ndpL, CI, CI,CI,CI, (long)ND*CI,sM,(long)ND*CI,
        nullptr,0.f,nullptr,nullptr,nullptr,nullptr,nullptr);

    // output convs: BN + residual, fp32 out
    gemm_cp<3,false,false><<<dim3(4,RA/128,1),blk,SMEM_BYTES>>>(napH,napL,WwH,WwL,
        out_na,nullptr,nullptr, CI, CI,C,C, 0,0,0,
        bw,0.f,gw,betw,mw,vw,aim);
    gemm_cp<3,false,false><<<dim3(4,RD/128,1),blk,SMEM_BYTES>>>(ndpH,ndpL,WqH,WqL,
        out_nd,nullptr,nullptr, CI, CI,C,C, 0,0,0,
        bq,0.f,gq,betq,mq,vq,detect);
}